// round 2
// baseline (speedup 1.0000x reference)
#include <cuda_runtime.h>
#include <cstdint>

#define NB    8
#define NPTS  4096
#define MSEL  1024
#define NC    64
#define KNBR  64
#define NCTR  (NB*MSEL)           // 8192
#define X_OUT_ELEMS (NCTR*256)    // 2097152
#define POS_OFF  X_OUT_ELEMS
#define BATCH_OFF (POS_OFF + NCTR*3)
#define SEED_OFF  (BATCH_OFF + NCTR)
#define TOTAL_OUT (SEED_OFF + NCTR)   // 2138112

// ---- scratch (static device globals: allocation-free rule) ----
__device__ int g_idx[NCTR];          // flat chosen indices (g*4096 + local)
__device__ int g_nbr[NCTR*KNBR];     // local neighbor indices per centroid
__device__ int g_cnt[NCTR];          // valid neighbor count (<= 64)

// ============================================================
// 1) Farthest point sampling: one block per graph, 1024 threads
//    Points live in REGISTERS (4 per thread) — no big smem.
// ============================================================
__global__ __launch_bounds__(1024) void fps_kernel(const float* __restrict__ pos) {
    __shared__ unsigned long long warpbest[32];
    __shared__ unsigned long long s_key;
    __shared__ float s_lx, s_ly, s_lz;

    int g = blockIdx.x;
    const float* p = pos + (size_t)g * NPTS * 3;
    int t = threadIdx.x;
    const int i0 = t * 4;

    // load my 4 points into registers
    float px[4], py[4], pz[4];
    #pragma unroll
    for (int j = 0; j < 4; j++) {
        px[j] = p[3*(i0+j)+0];
        py[j] = p[3*(i0+j)+1];
        pz[j] = p[3*(i0+j)+2];
    }
    float mn[4] = {1e10f, 1e10f, 1e10f, 1e10f};

    if (t == 0) {
        g_idx[g*MSEL] = g*NPTS;
        s_lx = px[0]; s_ly = py[0]; s_lz = pz[0];
    }
    __syncthreads();

    for (int it = 1; it < MSEL; it++) {
        float lx = s_lx, ly = s_ly, lz = s_lz;
        float bv = -1.0f; int bi = i0;
        #pragma unroll
        for (int j = 0; j < 4; j++) {
            float dx = __fsub_rn(px[j], lx);
            float dy = __fsub_rn(py[j], ly);
            float dz = __fsub_rn(pz[j], lz);
            float d  = __fadd_rn(__fadd_rn(__fmul_rn(dx,dx), __fmul_rn(dy,dy)), __fmul_rn(dz,dz));
            mn[j] = fminf(mn[j], d);
            if (mn[j] > bv) { bv = mn[j]; bi = i0 + j; }
        }
        // key = (valbits<<32) | (NPTS-1-idx): max-key => max value, tie -> lowest idx
        unsigned long long key =
            ((unsigned long long)__float_as_uint(bv) << 32) | (unsigned)(NPTS - 1 - bi);
        #pragma unroll
        for (int o = 16; o > 0; o >>= 1) {
            unsigned long long ok = __shfl_xor_sync(0xffffffffu, key, o);
            if (ok > key) key = ok;
        }
        if ((t & 31) == 0) warpbest[t >> 5] = key;
        __syncthreads();
        if (t < 32) {
            unsigned long long k2 = warpbest[t];
            #pragma unroll
            for (int o = 16; o > 0; o >>= 1) {
                unsigned long long ok = __shfl_xor_sync(0xffffffffu, k2, o);
                if (ok > k2) k2 = ok;
            }
            if (t == 0) s_key = k2;
        }
        __syncthreads();
        int nxt = NPTS - 1 - (int)(s_key & 0xffffffffu);
        if ((nxt >> 2) == t) {             // winner thread broadcasts coords
            int j = nxt & 3;
            s_lx = px[j]; s_ly = py[j]; s_lz = pz[j];
            g_idx[g*MSEL + it] = g*NPTS + nxt;
        }
        __syncthreads();
    }
}

// ============================================================
// 2) Radius search + exact top-64 (d2, idx)-lexicographic select
// ============================================================
#define CAP 1024
__global__ __launch_bounds__(256) void nbr_kernel(const float* __restrict__ pos) {
    __shared__ unsigned long long keys[CAP];
    __shared__ int s_cnt, s_osel;
    __shared__ float s_c[3];

    int c = blockIdx.x;           // centroid id
    int g = c >> 10;
    int t = threadIdx.x;
    if (t == 0) {
        int ci = g_idx[c];
        s_c[0] = pos[3*ci]; s_c[1] = pos[3*ci+1]; s_c[2] = pos[3*ci+2];
        s_cnt = 0; s_osel = 0;
    }
    __syncthreads();
    float cx = s_c[0], cy = s_c[1], cz = s_c[2];
    const float* p = pos + (size_t)g * NPTS * 3;
    const float RR = 0.04f;  // f32(0.2*0.2)

    for (int i = t; i < NPTS; i += 256) {
        float dx = __fsub_rn(cx, p[3*i]);
        float dy = __fsub_rn(cy, p[3*i+1]);
        float dz = __fsub_rn(cz, p[3*i+2]);
        float d2 = __fadd_rn(__fadd_rn(__fmul_rn(dx,dx), __fmul_rn(dy,dy)), __fmul_rn(dz,dz));
        if (d2 < RR) {
            int slot = atomicAdd(&s_cnt, 1);
            if (slot < CAP)
                keys[slot] = ((unsigned long long)__float_as_uint(d2) << 32) | (unsigned)i;
        }
    }
    __syncthreads();
    int cnt = min(s_cnt, CAP);
    if (cnt <= KNBR) {
        for (int j = t; j < cnt; j += 256)
            g_nbr[c*KNBR + j] = (int)(keys[j] & 0xffffffffu);
        if (t == 0) g_cnt[c] = cnt;
    } else {
        for (int j = t; j < cnt; j += 256) {
            unsigned long long kj = keys[j];
            int rank = 0;
            for (int q = 0; q < cnt; q++) rank += (keys[q] < kj);
            if (rank < KNBR) {
                int o = atomicAdd(&s_osel, 1);
                g_nbr[c*KNBR + o] = (int)(kj & 0xffffffffu);
            }
        }
        if (t == 0) g_cnt[c] = KNBR;
    }
}

// ============================================================
// 3) Fused MLP (67->128->128->256) + masked max-pool
//    1 centroid/block, 128 threads, two 32-row passes
// ============================================================
__global__ __launch_bounds__(128) void mlp_kernel(
    const float* __restrict__ x,  const float* __restrict__ pos,
    const float* __restrict__ W1, const float* __restrict__ b1,
    const float* __restrict__ W2, const float* __restrict__ b2,
    const float* __restrict__ W3, const float* __restrict__ b3,
    float* __restrict__ out)
{
    __shared__ float smsg[32][68];    // 67 cols + zero pad
    __shared__ float sh1[32][128];
    __shared__ float sh2[32][128];
    __shared__ int   s_nbr[KNBR];
    __shared__ float s_ctr[3];
    __shared__ int   s_n;

    int c = blockIdx.x;
    int g = c >> 10;
    int t = threadIdx.x;
    if (t == 0) {
        s_n = g_cnt[c];
        int ci = g_idx[c];
        s_ctr[0] = pos[3*ci]; s_ctr[1] = pos[3*ci+1]; s_ctr[2] = pos[3*ci+2];
    }
    if (t < KNBR) s_nbr[t] = g_nbr[c*KNBR + t];
    __syncthreads();
    int n = s_n;
    const float* xg = x   + (size_t)g * NPTS * NC;
    const float* pg = pos + (size_t)g * NPTS * 3;

    float runmax0 = -1e30f, runmax1 = -1e30f;

    for (int pass = 0; pass < 2; pass++) {
        if (pass == 1 && n <= 32) break;  // uniform across block
        // ---- build msg rows [pass*32, pass*32+32) ----
        for (int e = t; e < 32*68; e += 128) {
            int r = e / 68, k = e - r*68;
            int rg = pass*32 + r;
            float v = 0.f;
            if (rg < n) {
                int nb = s_nbr[rg];
                if (k < NC)        v = xg[nb*NC + k];
                else if (k < 67)   v = pg[3*nb + (k-64)] - s_ctr[k-64];
            }
            smsg[r][k] = v;
        }
        __syncthreads();
        // ---- layer 1: [32x67] @ [67x128] ----
        {
            float acc[32];
            #pragma unroll
            for (int r = 0; r < 32; r++) acc[r] = 0.f;
            for (int kc = 0; kc < 16; kc++) {
                int k = kc*4;
                float w0 = W1[(k+0)*128 + t], w1 = W1[(k+1)*128 + t];
                float w2 = W1[(k+2)*128 + t], w3 = W1[(k+3)*128 + t];
                #pragma unroll
                for (int r = 0; r < 32; r++) {
                    float4 m = *(const float4*)&smsg[r][k];
                    acc[r] = fmaf(m.x, w0, fmaf(m.y, w1, fmaf(m.z, w2, fmaf(m.w, w3, acc[r]))));
                }
            }
            {   // tail k = 64..66 (col 67 is zero pad)
                float w0 = W1[64*128 + t], w1 = W1[65*128 + t], w2 = W1[66*128 + t];
                #pragma unroll
                for (int r = 0; r < 32; r++) {
                    float4 m = *(const float4*)&smsg[r][64];
                    acc[r] = fmaf(m.x, w0, fmaf(m.y, w1, fmaf(m.z, w2, acc[r])));
                }
            }
            float bv = b1[t];
            #pragma unroll
            for (int r = 0; r < 32; r++) sh1[r][t] = fmaxf(acc[r] + bv, 0.f);
        }
        __syncthreads();
        // ---- layer 2: [32x128] @ [128x128] ----
        {
            float acc[32];
            #pragma unroll
            for (int r = 0; r < 32; r++) acc[r] = 0.f;
            for (int kc = 0; kc < 32; kc++) {
                int k = kc*4;
                float w0 = W2[(k+0)*128 + t], w1 = W2[(k+1)*128 + t];
                float w2 = W2[(k+2)*128 + t], w3 = W2[(k+3)*128 + t];
                #pragma unroll
                for (int r = 0; r < 32; r++) {
                    float4 m = *(const float4*)&sh1[r][k];
                    acc[r] = fmaf(m.x, w0, fmaf(m.y, w1, fmaf(m.z, w2, fmaf(m.w, w3, acc[r]))));
                }
            }
            float bv = b2[t];
            #pragma unroll
            for (int r = 0; r < 32; r++) sh2[r][t] = fmaxf(acc[r] + bv, 0.f);
        }
        __syncthreads();
        // ---- layer 3: [32x128] @ [128x256] + masked row-max ----
        for (int cp = 0; cp < 2; cp++) {
            int col = t + cp*128;
            float acc[32];
            #pragma unroll
            for (int r = 0; r < 32; r++) acc[r] = 0.f;
            for (int kc = 0; kc < 32; kc++) {
                int k = kc*4;
                float w0 = W3[(k+0)*256 + col], w1 = W3[(k+1)*256 + col];
                float w2 = W3[(k+2)*256 + col], w3 = W3[(k+3)*256 + col];
                #pragma unroll
                for (int r = 0; r < 32; r++) {
                    float4 m = *(const float4*)&sh2[r][k];
                    acc[r] = fmaf(m.x, w0, fmaf(m.y, w1, fmaf(m.z, w2, fmaf(m.w, w3, acc[r]))));
                }
            }
            float bv = b3[col];
            float rm = (cp == 0) ? runmax0 : runmax1;
            #pragma unroll
            for (int r = 0; r < 32; r++) {
                float v = fmaxf(acc[r] + bv, 0.f);
                int rg = pass*32 + r;
                if (rg < n) rm = fmaxf(rm, v);
            }
            if (cp == 0) runmax0 = rm; else runmax1 = rm;
        }
        __syncthreads();
    }
    out[(size_t)c*256 + t]       = (n > 0) ? runmax0 : 0.f;
    out[(size_t)c*256 + 128 + t] = (n > 0) ? runmax1 : 0.f;
}

// ============================================================
// 4) Tail outputs: pos_out / batch_out / seed_out
// ============================================================
__global__ void tail_kernel(const float* __restrict__ pos, float* __restrict__ out,
                            int write_tail) {
    int i = blockIdx.x * blockDim.x + threadIdx.x;
    if (i >= NCTR || !write_tail) return;
    int fi = g_idx[i];
    out[POS_OFF + 3*i + 0] = pos[3*fi + 0];
    out[POS_OFF + 3*i + 1] = pos[3*fi + 1];
    out[POS_OFF + 3*i + 2] = pos[3*fi + 2];
    out[BATCH_OFF + i] = (float)(fi >> 12);   // graph id = fi / 4096
    out[SEED_OFF  + i] = (float)fi;           // seed_idx = arange -> fi
}

// ============================================================
extern "C" void kernel_launch(void* const* d_in, const int* in_sizes, int n_in,
                              void* d_out, int out_size) {
    const float* x   = (const float*)d_in[0];
    const float* pos = (const float*)d_in[1];
    // d_in[2] = batch, d_in[3] = seed_idx (recomputed from indices; unused)
    const float* W1 = (const float*)d_in[4];
    const float* b1 = (const float*)d_in[5];
    const float* W2 = (const float*)d_in[6];
    const float* b2 = (const float*)d_in[7];
    const float* W3 = (const float*)d_in[8];
    const float* b3 = (const float*)d_in[9];
    float* out = (float*)d_out;

    fps_kernel<<<NB, 1024>>>(pos);
    nbr_kernel<<<NCTR, 256>>>(pos);
    mlp_kernel<<<NCTR, 128>>>(x, pos, W1, b1, W2, b2, W3, b3, out);
    tail_kernel<<<(NCTR + 255)/256, 256>>>(pos, out, out_size >= TOTAL_OUT ? 1 : 0);
}

// round 5
// speedup vs baseline: 2.3607x; 2.3607x over previous
#include <cuda_runtime.h>
#include <cuda_fp16.h>
#include <cstdint>

#define NB    8
#define NPTS  4096
#define MSEL  1024
#define NC    64
#define KNBR  64
#define NCTR  (NB*MSEL)           // 8192
#define X_OUT_ELEMS (NCTR*256)
#define POS_OFF  X_OUT_ELEMS
#define BATCH_OFF (POS_OFF + NCTR*3)
#define SEED_OFF  (BATCH_OFF + NCTR)
#define TOTAL_OUT (SEED_OFF + NCTR)

// ---- global scratch (static: allocation-free rule) ----
__device__ int   g_idx[NCTR];
__device__ int   g_nbr[NCTR*KNBR];
__device__ int   g_cnt[NCTR];
__device__ float qb_g[(size_t)NB*NPTS*128];   // per-point layer1 pre-activation (+b1)

// ============================================================
// 1) FPS (unchanged, known-correct)
// ============================================================
__global__ __launch_bounds__(1024) void fps_kernel(const float* __restrict__ pos) {
    __shared__ unsigned long long warpbest[32];
    __shared__ unsigned long long s_key;
    __shared__ float s_lx, s_ly, s_lz;
    int g = blockIdx.x;
    const float* p = pos + (size_t)g * NPTS * 3;
    int t = threadIdx.x;
    const int i0 = t * 4;
    float px[4], py[4], pz[4];
    #pragma unroll
    for (int j = 0; j < 4; j++) {
        px[j] = p[3*(i0+j)+0]; py[j] = p[3*(i0+j)+1]; pz[j] = p[3*(i0+j)+2];
    }
    float mn[4] = {1e10f, 1e10f, 1e10f, 1e10f};
    if (t == 0) { g_idx[g*MSEL] = g*NPTS; s_lx = px[0]; s_ly = py[0]; s_lz = pz[0]; }
    __syncthreads();
    for (int it = 1; it < MSEL; it++) {
        float lx = s_lx, ly = s_ly, lz = s_lz;
        float bv = -1.0f; int bi = i0;
        #pragma unroll
        for (int j = 0; j < 4; j++) {
            float dx = __fsub_rn(px[j], lx), dy = __fsub_rn(py[j], ly), dz = __fsub_rn(pz[j], lz);
            float d  = __fadd_rn(__fadd_rn(__fmul_rn(dx,dx), __fmul_rn(dy,dy)), __fmul_rn(dz,dz));
            mn[j] = fminf(mn[j], d);
            if (mn[j] > bv) { bv = mn[j]; bi = i0 + j; }
        }
        unsigned long long key =
            ((unsigned long long)__float_as_uint(bv) << 32) | (unsigned)(NPTS - 1 - bi);
        #pragma unroll
        for (int o = 16; o > 0; o >>= 1) {
            unsigned long long ok = __shfl_xor_sync(0xffffffffu, key, o);
            if (ok > key) key = ok;
        }
        if ((t & 31) == 0) warpbest[t >> 5] = key;
        __syncthreads();
        if (t < 32) {
            unsigned long long k2 = warpbest[t];
            #pragma unroll
            for (int o = 16; o > 0; o >>= 1) {
                unsigned long long ok = __shfl_xor_sync(0xffffffffu, k2, o);
                if (ok > k2) k2 = ok;
            }
            if (t == 0) s_key = k2;
        }
        __syncthreads();
        int nxt = NPTS - 1 - (int)(s_key & 0xffffffffu);
        if ((nxt >> 2) == t) {
            int j = nxt & 3;
            s_lx = px[j]; s_ly = py[j]; s_lz = pz[j];
            g_idx[g*MSEL + it] = g*NPTS + nxt;
        }
        __syncthreads();
    }
}

// ============================================================
// 2) Radius + top-64 (unchanged, known-correct)
// ============================================================
#define CAP 1024
__global__ __launch_bounds__(256) void nbr_kernel(const float* __restrict__ pos) {
    __shared__ unsigned long long keys[CAP];
    __shared__ int s_cnt, s_osel;
    __shared__ float s_c[3];
    int c = blockIdx.x;
    int g = c >> 10;
    int t = threadIdx.x;
    if (t == 0) {
        int ci = g_idx[c];
        s_c[0] = pos[3*ci]; s_c[1] = pos[3*ci+1]; s_c[2] = pos[3*ci+2];
        s_cnt = 0; s_osel = 0;
    }
    __syncthreads();
    float cx = s_c[0], cy = s_c[1], cz = s_c[2];
    const float* p = pos + (size_t)g * NPTS * 3;
    const float RR = 0.04f;
    for (int i = t; i < NPTS; i += 256) {
        float dx = __fsub_rn(cx, p[3*i]);
        float dy = __fsub_rn(cy, p[3*i+1]);
        float dz = __fsub_rn(cz, p[3*i+2]);
        float d2 = __fadd_rn(__fadd_rn(__fmul_rn(dx,dx), __fmul_rn(dy,dy)), __fmul_rn(dz,dz));
        if (d2 < RR) {
            int slot = atomicAdd(&s_cnt, 1);
            if (slot < CAP)
                keys[slot] = ((unsigned long long)__float_as_uint(d2) << 32) | (unsigned)i;
        }
    }
    __syncthreads();
    int cnt = min(s_cnt, CAP);
    if (cnt <= KNBR) {
        for (int j = t; j < cnt; j += 256)
            g_nbr[c*KNBR + j] = (int)(keys[j] & 0xffffffffu);
        if (t == 0) g_cnt[c] = cnt;
    } else {
        for (int j = t; j < cnt; j += 256) {
            unsigned long long kj = keys[j];
            int rank = 0;
            for (int q = 0; q < cnt; q++) rank += (keys[q] < kj);
            if (rank < KNBR) {
                int o = atomicAdd(&s_osel, 1);
                g_nbr[c*KNBR + o] = (int)(kj & 0xffffffffu);
            }
        }
        if (t == 0) g_cnt[c] = KNBR;
    }
}

// ============================================================
// 3a) Per-point layer-1: qb[p] = x_p@W1[:64] + pos_p@W1[64:67] + b1
// ============================================================
__global__ __launch_bounds__(128) void qb_kernel(
    const float* __restrict__ x, const float* __restrict__ pos,
    const float* __restrict__ W1, const float* __restrict__ b1)
{
    __shared__ float sx[64];
    __shared__ float sp[3];
    int p = blockIdx.x, t = threadIdx.x;
    if (t < 64) sx[t] = x[(size_t)p*64 + t];
    if (t < 3)  sp[t] = pos[(size_t)p*3 + t];
    __syncthreads();
    float acc = b1[t];
    #pragma unroll 8
    for (int k = 0; k < 64; k++) acc = fmaf(sx[k], W1[k*128 + t], acc);
    acc = fmaf(sp[0], W1[64*128 + t], acc);
    acc = fmaf(sp[1], W1[65*128 + t], acc);
    acc = fmaf(sp[2], W1[66*128 + t], acc);
    qb_g[(size_t)p*128 + t] = acc;
}

// ============================================================
// 3b) Persistent fused edge MLP (layers 2+3) via mma.sync fp16
//     grid 148 blocks x 128 threads; each block loops tiles of
//     2 centroids (M = 128 edge rows). Weights in smem once.
// ============================================================
#define STR    272              // padded row stride bytes (136 fp16)
#define O_W2T  0u               // 128 * 272 = 34816
#define O_W3T  34816u           // 256 * 272 = 69632
#define O_A1   104448u          // 34816
#define O_H2   139264u          // 34816
#define O_B2   174080u          // 128 f
#define O_B3   174592u          // 256 f
#define O_PART 175616u          // 4*256 f
#define O_S    179712u          // 2*128 f
#define O_META 180736u          // 2 ints
#define O_CTR  180744u          // 6 f
#define SMEM_EDGE 180800

__device__ __forceinline__ void mma16816(float* d, const uint32_t* a,
                                         uint32_t b0, uint32_t b1) {
    asm volatile("mma.sync.aligned.m16n8k16.row.col.f32.f16.f16.f32 "
        "{%0,%1,%2,%3}, {%4,%5,%6,%7}, {%8,%9}, {%0,%1,%2,%3};"
        : "+f"(d[0]), "+f"(d[1]), "+f"(d[2]), "+f"(d[3])
        : "r"(a[0]), "r"(a[1]), "r"(a[2]), "r"(a[3]), "r"(b0), "r"(b1));
}
__device__ __forceinline__ uint32_t packh2(float a, float b) {
    __half2 h = __floats2half2_rn(a, b);
    return *(uint32_t*)&h;
}

__global__ __launch_bounds__(128, 1) void edge_kernel(
    const float* __restrict__ pos, const float* __restrict__ W1,
    const float* __restrict__ W2, const float* __restrict__ b2,
    const float* __restrict__ W3, const float* __restrict__ b3,
    float* __restrict__ out)
{
    extern __shared__ char sm[];
    float* b2s  = (float*)(sm + O_B2);
    float* b3s  = (float*)(sm + O_B3);
    float* part = (float*)(sm + O_PART);
    float* s_sm = (float*)(sm + O_S);
    int*   meta = (int*)(sm + O_META);
    float* ctr  = (float*)(sm + O_CTR);

    int t = threadIdx.x, wid = t >> 5, lane = t & 31;
    int g4 = lane >> 2, tig = lane & 3;
    int m0 = wid * 32;

    // ---- one-time: weights -> fp16 padded smem (transposed: [n][k]) ----
    for (int idx = t; idx < 128*128; idx += 128) {
        int k = idx >> 7, n = idx & 127;
        *(__half*)(sm + O_W2T + (uint32_t)n*STR + k*2) = __float2half_rn(W2[idx]);
    }
    for (int idx = t; idx < 128*256; idx += 128) {
        int k = idx >> 8, n = idx & 255;
        *(__half*)(sm + O_W3T + (uint32_t)n*STR + k*2) = __float2half_rn(W3[idx]);
    }
    b2s[t] = b2[t]; b3s[t] = b3[t]; b3s[128 + t] = b3[128 + t];
    float w1x = W1[64*128 + t], w1y = W1[65*128 + t], w1z = W1[66*128 + t];
    __syncthreads();

    for (int tile = blockIdx.x; tile < NCTR/2; tile += 148) {
        int c0 = 2 * tile;
        int g  = c0 >> 10;
        if (t < 2) {
            meta[t] = g_cnt[c0 + t];
            int ci = g_idx[c0 + t];
            ctr[t*3+0] = pos[3*ci]; ctr[t*3+1] = pos[3*ci+1]; ctr[t*3+2] = pos[3*ci+2];
        }
        __syncthreads();
        s_sm[t]       = ctr[0]*w1x + ctr[1]*w1y + ctr[2]*w1z;
        s_sm[128 + t] = ctr[3]*w1x + ctr[4]*w1y + ctr[5]*w1z;
        __syncthreads();

        // ---- A1 build: row r = t, h1 = relu(qb[j] - s[cl]) fp16 ----
        {
            int r = t, cl = r >> 6;
            bool valid = (r & 63) < meta[cl];
            int jg = valid ? (g*NPTS + g_nbr[(c0 + cl)*KNBR + (r & 63)]) : 0;
            const float4* qrow = (const float4*)(qb_g + (size_t)jg * 128);
            const float4* sv   = (const float4*)(s_sm + cl*128);
            char* arow = sm + O_A1 + (uint32_t)r*STR;
            #pragma unroll
            for (int i = 0; i < 32; i++) {
                uint32_t u0 = 0, u1 = 0;
                if (valid) {
                    float4 q = qrow[i], s4 = sv[i];
                    u0 = packh2(fmaxf(q.x - s4.x, 0.f), fmaxf(q.y - s4.y, 0.f));
                    u1 = packh2(fmaxf(q.z - s4.z, 0.f), fmaxf(q.w - s4.w, 0.f));
                }
                *(uint32_t*)(arow + i*8)     = u0;
                *(uint32_t*)(arow + i*8 + 4) = u1;
            }
        }
        __syncwarp();

        // ---- layer 2: h2 = relu(A1 @ W2 + b2), per-warp 32 rows ----
        {
            float acc[2][16][4];
            #pragma unroll
            for (int mt = 0; mt < 2; mt++)
                #pragma unroll
                for (int n = 0; n < 16; n++)
                    #pragma unroll
                    for (int q = 0; q < 4; q++) acc[mt][n][q] = 0.f;
            #pragma unroll
            for (int k = 0; k < 8; k++) {
                uint32_t a[2][4];
                #pragma unroll
                for (int mt = 0; mt < 2; mt++) {
                    const char* base = sm + O_A1 + (uint32_t)(m0 + mt*16 + g4)*STR + k*32 + tig*4;
                    a[mt][0] = *(const uint32_t*)(base);
                    a[mt][1] = *(const uint32_t*)(base + 8*STR);
                    a[mt][2] = *(const uint32_t*)(base + 16);
                    a[mt][3] = *(const uint32_t*)(base + 8*STR + 16);
                }
                #pragma unroll
                for (int n = 0; n < 16; n++) {
                    const char* bb = sm + O_W2T + (uint32_t)(n*8 + g4)*STR + k*32 + tig*4;
                    uint32_t b0 = *(const uint32_t*)(bb);
                    uint32_t b1 = *(const uint32_t*)(bb + 16);
                    mma16816(acc[0][n], a[0], b0, b1);
                    mma16816(acc[1][n], a[1], b0, b1);
                }
            }
            #pragma unroll
            for (int mt = 0; mt < 2; mt++) {
                int r0 = m0 + mt*16 + g4;
                #pragma unroll
                for (int n = 0; n < 16; n++) {
                    int col = n*8 + tig*2;
                    *(uint32_t*)(sm + O_H2 + (uint32_t)r0*STR + col*2) =
                        packh2(fmaxf(acc[mt][n][0] + b2s[col], 0.f),
                               fmaxf(acc[mt][n][1] + b2s[col+1], 0.f));
                    *(uint32_t*)(sm + O_H2 + (uint32_t)(r0+8)*STR + col*2) =
                        packh2(fmaxf(acc[mt][n][2] + b2s[col], 0.f),
                               fmaxf(acc[mt][n][3] + b2s[col+1], 0.f));
                }
            }
        }
        __syncwarp();

        // ---- layer 3: relu(h2 @ W3 + b3), mask, column-max ----
        {
            int ncnt = meta[wid >> 1];
            int rb0  = (wid & 1) * 32;
            #pragma unroll
            for (int nh = 0; nh < 2; nh++) {
                float acc[2][16][4];
                #pragma unroll
                for (int mt = 0; mt < 2; mt++)
                    #pragma unroll
                    for (int n = 0; n < 16; n++)
                        #pragma unroll
                        for (int q = 0; q < 4; q++) acc[mt][n][q] = 0.f;
                #pragma unroll
                for (int k = 0; k < 8; k++) {
                    uint32_t a[2][4];
                    #pragma unroll
                    for (int mt = 0; mt < 2; mt++) {
                        const char* base = sm + O_H2 + (uint32_t)(m0 + mt*16 + g4)*STR + k*32 + tig*4;
                        a[mt][0] = *(const uint32_t*)(base);
                        a[mt][1] = *(const uint32_t*)(base + 8*STR);
                        a[mt][2] = *(const uint32_t*)(base + 16);
                        a[mt][3] = *(const uint32_t*)(base + 8*STR + 16);
                    }
                    #pragma unroll
                    for (int n = 0; n < 16; n++) {
                        const char* bb = sm + O_W3T + (uint32_t)(nh*128 + n*8 + g4)*STR + k*32 + tig*4;
                        uint32_t b0 = *(const uint32_t*)(bb);
                        uint32_t b1 = *(const uint32_t*)(bb + 16);
                        mma16816(acc[0][n], a[0], b0, b1);
                        mma16816(acc[1][n], a[1], b0, b1);
                    }
                }
                #pragma unroll
                for (int n = 0; n < 16; n++) {
                    int col = nh*128 + n*8 + tig*2;
                    float bv0 = b3s[col], bv1 = b3s[col+1];
                    float mx0 = -1e30f, mx1 = -1e30f;
                    #pragma unroll
                    for (int mt = 0; mt < 2; mt++) {
                        int rlo = rb0 + mt*16 + g4;
                        bool vlo = rlo < ncnt, vhi = (rlo + 8) < ncnt;
                        if (vlo) {
                            mx0 = fmaxf(mx0, fmaxf(acc[mt][n][0] + bv0, 0.f));
                            mx1 = fmaxf(mx1, fmaxf(acc[mt][n][1] + bv1, 0.f));
                        }
                        if (vhi) {
                            mx0 = fmaxf(mx0, fmaxf(acc[mt][n][2] + bv0, 0.f));
                            mx1 = fmaxf(mx1, fmaxf(acc[mt][n][3] + bv1, 0.f));
                        }
                    }
                    #pragma unroll
                    for (int o = 4; o <= 16; o <<= 1) {
                        mx0 = fmaxf(mx0, __shfl_xor_sync(0xffffffffu, mx0, o));
                        mx1 = fmaxf(mx1, __shfl_xor_sync(0xffffffffu, mx1, o));
                    }
                    if (g4 == 0) {
                        part[wid*256 + col]     = mx0;
                        part[wid*256 + col + 1] = mx1;
                    }
                }
            }
        }
        __syncthreads();

        int n0 = meta[0], n1 = meta[1];
        #pragma unroll
        for (int rep = 0; rep < 2; rep++) {
            int col = t + rep*128;
            float m0v = fmaxf(part[0*256 + col], part[1*256 + col]);
            float m1v = fmaxf(part[2*256 + col], part[3*256 + col]);
            out[(size_t)c0*256 + col]     = (n0 > 0) ? m0v : 0.f;
            out[(size_t)(c0+1)*256 + col] = (n1 > 0) ? m1v : 0.f;
        }
        __syncthreads();
    }
}

// ============================================================
// 4) Tail outputs
// ============================================================
__global__ void tail_kernel(const float* __restrict__ pos, float* __restrict__ out,
                            int write_tail) {
    int i = blockIdx.x * blockDim.x + threadIdx.x;
    if (i >= NCTR || !write_tail) return;
    int fi = g_idx[i];
    out[POS_OFF + 3*i + 0] = pos[3*fi + 0];
    out[POS_OFF + 3*i + 1] = pos[3*fi + 1];
    out[POS_OFF + 3*i + 2] = pos[3*fi + 2];
    out[BATCH_OFF + i] = (float)(fi >> 12);
    out[SEED_OFF  + i] = (float)fi;
}

// ============================================================
extern "C" void kernel_launch(void* const* d_in, const int* in_sizes, int n_in,
                              void* d_out, int out_size) {
    const float* x   = (const float*)d_in[0];
    const float* pos = (const float*)d_in[1];
    const float* W1  = (const float*)d_in[4];
    const float* b1  = (const float*)d_in[5];
    const float* W2  = (const float*)d_in[6];
    const float* b2  = (const float*)d_in[7];
    const float* W3  = (const float*)d_in[8];
    const float* b3  = (const float*)d_in[9];
    float* out = (float*)d_out;

    cudaFuncSetAttribute(edge_kernel, cudaFuncAttributeMaxDynamicSharedMemorySize, SMEM_EDGE);

    fps_kernel<<<NB, 1024>>>(pos);
    nbr_kernel<<<NCTR, 256>>>(pos);
    qb_kernel<<<NB*NPTS, 128>>>(x, pos, W1, b1);
    edge_kernel<<<148, 128, SMEM_EDGE>>>(pos, W1, W2, b2, W3, b3, out);
    tail_kernel<<<(NCTR + 255)/256, 256>>>(pos, out, out_size >= TOTAL_OUT ? 1 : 0);
}

// round 6
// speedup vs baseline: 3.0863x; 1.3073x over previous
#include <cuda_runtime.h>
#include <cuda_fp16.h>
#include <cstdint>

#define NB    8
#define NPTS  4096
#define MSEL  1024
#define NC    64
#define KNBR  64
#define NCTR  (NB*MSEL)           // 8192
#define X_OUT_ELEMS (NCTR*256)
#define POS_OFF  X_OUT_ELEMS
#define BATCH_OFF (POS_OFF + NCTR*3)
#define SEED_OFF  (BATCH_OFF + NCTR)
#define TOTAL_OUT (SEED_OFF + NCTR)

// ---- global scratch (static: allocation-free rule) ----
__device__ int   g_idx[NCTR];
__device__ int   g_nbr[NCTR*KNBR];
__device__ int   g_cnt[NCTR];
__device__ float qb_g[(size_t)NB*NPTS*128];   // per-point layer1 pre-activation (+b1)

// ============================================================
// 1) FPS: 512 threads x 8 pts, smem pos cache, 1 barrier/iter
// ============================================================
#define FPS_SMEM (3*NPTS*4 + 512)
__global__ __launch_bounds__(512) void fps_kernel(const float* __restrict__ pos) {
    extern __shared__ float fsm[];
    float* sx = fsm;
    float* sy = fsm + NPTS;
    float* sz = fsm + 2*NPTS;
    unsigned long long* warpbest = (unsigned long long*)(fsm + 3*NPTS);  // [2][16]

    int g = blockIdx.x;
    const float* p = pos + (size_t)g * NPTS * 3;
    int t = threadIdx.x, lane = t & 31, wid = t >> 5;

    for (int i = t; i < NPTS; i += 512) {
        sx[i] = p[3*i]; sy[i] = p[3*i+1]; sz[i] = p[3*i+2];
    }
    __syncthreads();

    const int i0 = t * 8;
    float px[8], py[8], pz[8], mn[8];
    #pragma unroll
    for (int j = 0; j < 8; j++) {
        px[j] = sx[i0+j]; py[j] = sy[i0+j]; pz[j] = sz[i0+j]; mn[j] = 1e10f;
    }
    float lx = sx[0], ly = sy[0], lz = sz[0];
    if (t == 0) g_idx[g*MSEL] = g*NPTS;

    for (int it = 1; it < MSEL; it++) {
        float bv = -1.0f; int bi = i0;
        #pragma unroll
        for (int j = 0; j < 8; j++) {
            float dx = __fsub_rn(px[j], lx), dy = __fsub_rn(py[j], ly), dz = __fsub_rn(pz[j], lz);
            float d  = __fadd_rn(__fadd_rn(__fmul_rn(dx,dx), __fmul_rn(dy,dy)), __fmul_rn(dz,dz));
            mn[j] = fminf(mn[j], d);
            if (mn[j] > bv) { bv = mn[j]; bi = i0 + j; }
        }
        // key: max value, tie -> lowest index
        unsigned long long key =
            ((unsigned long long)__float_as_uint(bv) << 32) | (unsigned)(NPTS - 1 - bi);
        #pragma unroll
        for (int o = 16; o > 0; o >>= 1) {
            unsigned long long ok = __shfl_xor_sync(0xffffffffu, key, o);
            if (ok > key) key = ok;
        }
        if (lane == 0) warpbest[(it & 1)*16 + wid] = key;
        __syncthreads();
        // every warp redundantly reduces the 16 leader keys (no 2nd barrier)
        unsigned long long k2 = warpbest[(it & 1)*16 + (lane & 15)];
        #pragma unroll
        for (int o = 8; o > 0; o >>= 1) {
            unsigned long long ok = __shfl_xor_sync(0xffffffffu, k2, o);
            if (ok > k2) k2 = ok;
        }
        int nxt = NPTS - 1 - (int)(k2 & 0xffffffffu);
        lx = sx[nxt]; ly = sy[nxt]; lz = sz[nxt];
        if (t == 0) g_idx[g*MSEL + it] = g*NPTS + nxt;
    }
}

// ============================================================
// 2) Radius + top-64 (unchanged, known-correct)
// ============================================================
#define CAP 1024
__global__ __launch_bounds__(256) void nbr_kernel(const float* __restrict__ pos) {
    __shared__ unsigned long long keys[CAP];
    __shared__ int s_cnt, s_osel;
    __shared__ float s_c[3];
    int c = blockIdx.x;
    int g = c >> 10;
    int t = threadIdx.x;
    if (t == 0) {
        int ci = g_idx[c];
        s_c[0] = pos[3*ci]; s_c[1] = pos[3*ci+1]; s_c[2] = pos[3*ci+2];
        s_cnt = 0; s_osel = 0;
    }
    __syncthreads();
    float cx = s_c[0], cy = s_c[1], cz = s_c[2];
    const float* p = pos + (size_t)g * NPTS * 3;
    const float RR = 0.04f;
    for (int i = t; i < NPTS; i += 256) {
        float dx = __fsub_rn(cx, p[3*i]);
        float dy = __fsub_rn(cy, p[3*i+1]);
        float dz = __fsub_rn(cz, p[3*i+2]);
        float d2 = __fadd_rn(__fadd_rn(__fmul_rn(dx,dx), __fmul_rn(dy,dy)), __fmul_rn(dz,dz));
        if (d2 < RR) {
            int slot = atomicAdd(&s_cnt, 1);
            if (slot < CAP)
                keys[slot] = ((unsigned long long)__float_as_uint(d2) << 32) | (unsigned)i;
        }
    }
    __syncthreads();
    int cnt = min(s_cnt, CAP);
    if (cnt <= KNBR) {
        for (int j = t; j < cnt; j += 256)
            g_nbr[c*KNBR + j] = (int)(keys[j] & 0xffffffffu);
        if (t == 0) g_cnt[c] = cnt;
    } else {
        for (int j = t; j < cnt; j += 256) {
            unsigned long long kj = keys[j];
            int rank = 0;
            for (int q = 0; q < cnt; q++) rank += (keys[q] < kj);
            if (rank < KNBR) {
                int o = atomicAdd(&s_osel, 1);
                g_nbr[c*KNBR + o] = (int)(kj & 0xffffffffu);
            }
        }
        if (t == 0) g_cnt[c] = KNBR;
    }
}

// ============================================================
// 3a) Per-point layer-1, 16 points/block (W1 reuse x16)
// ============================================================
#define QPB 16
__global__ __launch_bounds__(128) void qb_kernel(
    const float* __restrict__ x, const float* __restrict__ pos,
    const float* __restrict__ W1, const float* __restrict__ b1)
{
    __shared__ float sx[QPB*68];
    __shared__ float sp[QPB*3];
    int base = blockIdx.x * QPB;
    int t = threadIdx.x;
    for (int idx = t; idx < QPB*64; idx += 128) {
        int pp = idx >> 6, k = idx & 63;
        sx[pp*68 + k] = x[(size_t)(base + pp)*64 + k];
    }
    if (t < QPB*3) sp[t] = pos[(size_t)base*3 + t];
    __syncthreads();
    float acc[QPB];
    float bb = b1[t];
    #pragma unroll
    for (int q = 0; q < QPB; q++) acc[q] = bb;
    for (int k = 0; k < 64; k++) {
        float w = W1[k*128 + t];
        #pragma unroll
        for (int q = 0; q < QPB; q++) acc[q] = fmaf(sx[q*68 + k], w, acc[q]);
    }
    float wx = W1[64*128 + t], wy = W1[65*128 + t], wz = W1[66*128 + t];
    #pragma unroll
    for (int q = 0; q < QPB; q++) {
        acc[q] = fmaf(sp[q*3+0], wx, acc[q]);
        acc[q] = fmaf(sp[q*3+1], wy, acc[q]);
        acc[q] = fmaf(sp[q*3+2], wz, acc[q]);
        qb_g[(size_t)(base + q)*128 + t] = acc[q];
    }
}

// ============================================================
// 3b) Persistent fused edge MLP: 256 thr, 4 centroids/tile
// ============================================================
#define STR    272              // padded row stride bytes (136 fp16)
#define O_W2T  0u               // 128*272 = 34816
#define O_W3T  34816u           // 256*272 = 69632 -> 104448
#define O_AH   104448u          // 256*272 = 69632 -> 174080 (A1 & H2 aliased)
#define O_B2   174080u
#define O_B3   174592u
#define O_PART 175616u          // 8*256*4 = 8192 -> 183808
#define O_S    183808u          // 4*128*4 = 2048 -> 185856
#define O_META 185856u
#define O_CTR  185872u
#define SMEM_EDGE 185984

__device__ __forceinline__ void mma16816(float* d, const uint32_t* a,
                                         uint32_t b0, uint32_t b1) {
    asm volatile("mma.sync.aligned.m16n8k16.row.col.f32.f16.f16.f32 "
        "{%0,%1,%2,%3}, {%4,%5,%6,%7}, {%8,%9}, {%0,%1,%2,%3};"
        : "+f"(d[0]), "+f"(d[1]), "+f"(d[2]), "+f"(d[3])
        : "r"(a[0]), "r"(a[1]), "r"(a[2]), "r"(a[3]), "r"(b0), "r"(b1));
}
__device__ __forceinline__ uint32_t packh2(float a, float b) {
    __half2 h = __floats2half2_rn(a, b);
    return *(uint32_t*)&h;
}

__global__ __launch_bounds__(256, 1) void edge_kernel(
    const float* __restrict__ pos, const float* __restrict__ W1,
    const float* __restrict__ W2, const float* __restrict__ b2,
    const float* __restrict__ W3, const float* __restrict__ b3,
    float* __restrict__ out)
{
    extern __shared__ char sm[];
    float* b2s  = (float*)(sm + O_B2);
    float* b3s  = (float*)(sm + O_B3);
    float* part = (float*)(sm + O_PART);
    float* s_sm = (float*)(sm + O_S);
    int*   meta = (int*)(sm + O_META);
    float* ctr  = (float*)(sm + O_CTR);

    int t = threadIdx.x, wid = t >> 5, lane = t & 31;
    int g4 = lane >> 2, tig = lane & 3;
    int m0 = wid * 32;
    int colid = t & 127;

    // one-time: weights -> fp16 padded smem (transposed [n][k])
    for (int idx = t; idx < 128*128; idx += 256) {
        int k = idx >> 7, n = idx & 127;
        *(__half*)(sm + O_W2T + (uint32_t)n*STR + k*2) = __float2half_rn(W2[idx]);
    }
    for (int idx = t; idx < 128*256; idx += 256) {
        int k = idx >> 8, n = idx & 255;
        *(__half*)(sm + O_W3T + (uint32_t)n*STR + k*2) = __float2half_rn(W3[idx]);
    }
    if (t < 128) { b2s[t] = b2[t]; b3s[t] = b3[t]; b3s[128 + t] = b3[128 + t]; }
    float w1x = W1[64*128 + colid], w1y = W1[65*128 + colid], w1z = W1[66*128 + colid];
    __syncthreads();

    for (int tile = blockIdx.x; tile < NCTR/4; tile += 148) {
        int c0 = 4 * tile;
        int g  = c0 >> 10;
        if (t < 4) {
            meta[t] = g_cnt[c0 + t];
            int ci = g_idx[c0 + t];
            ctr[t*3+0] = pos[3*ci]; ctr[t*3+1] = pos[3*ci+1]; ctr[t*3+2] = pos[3*ci+2];
        }
        __syncthreads();
        {
            int cl0 = t >> 7;            // 0 or 1
            s_sm[t]       = ctr[cl0*3+0]*w1x + ctr[cl0*3+1]*w1y + ctr[cl0*3+2]*w1z;
            s_sm[t + 256] = ctr[(cl0+2)*3+0]*w1x + ctr[(cl0+2)*3+1]*w1y + ctr[(cl0+2)*3+2]*w1z;
        }
        __syncthreads();

        // A1 build: row r = t (256 rows = 4 centroids x 64)
        {
            int r = t, cl = r >> 6;
            bool valid = (r & 63) < meta[cl];
            int jg = valid ? (g*NPTS + g_nbr[(c0 + cl)*KNBR + (r & 63)]) : 0;
            const float4* qrow = (const float4*)(qb_g + (size_t)jg * 128);
            const float4* sv   = (const float4*)(s_sm + cl*128);
            char* arow = sm + O_AH + (uint32_t)r*STR;
            #pragma unroll
            for (int i = 0; i < 32; i++) {
                uint32_t u0 = 0, u1 = 0;
                if (valid) {
                    float4 q = qrow[i], s4 = sv[i];
                    u0 = packh2(fmaxf(q.x - s4.x, 0.f), fmaxf(q.y - s4.y, 0.f));
                    u1 = packh2(fmaxf(q.z - s4.z, 0.f), fmaxf(q.w - s4.w, 0.f));
                }
                *(uint32_t*)(arow + i*8)     = u0;
                *(uint32_t*)(arow + i*8 + 4) = u1;
            }
        }
        __syncwarp();

        // layer 2: h2 = relu(A1 @ W2 + b2); H2 overwrites A1 (own rows only)
        {
            float acc[2][16][4];
            #pragma unroll
            for (int mt = 0; mt < 2; mt++)
                #pragma unroll
                for (int n = 0; n < 16; n++)
                    #pragma unroll
                    for (int q = 0; q < 4; q++) acc[mt][n][q] = 0.f;
            #pragma unroll
            for (int k = 0; k < 8; k++) {
                uint32_t a[2][4];
                #pragma unroll
                for (int mt = 0; mt < 2; mt++) {
                    const char* base = sm + O_AH + (uint32_t)(m0 + mt*16 + g4)*STR + k*32 + tig*4;
                    a[mt][0] = *(const uint32_t*)(base);
                    a[mt][1] = *(const uint32_t*)(base + 8*STR);
                    a[mt][2] = *(const uint32_t*)(base + 16);
                    a[mt][3] = *(const uint32_t*)(base + 8*STR + 16);
                }
                #pragma unroll
                for (int n = 0; n < 16; n++) {
                    const char* bb = sm + O_W2T + (uint32_t)(n*8 + g4)*STR + k*32 + tig*4;
                    uint32_t b0 = *(const uint32_t*)(bb);
                    uint32_t b1 = *(const uint32_t*)(bb + 16);
                    mma16816(acc[0][n], a[0], b0, b1);
                    mma16816(acc[1][n], a[1], b0, b1);
                }
            }
            #pragma unroll
            for (int mt = 0; mt < 2; mt++) {
                int r0 = m0 + mt*16 + g4;
                #pragma unroll
                for (int n = 0; n < 16; n++) {
                    int col = n*8 + tig*2;
                    *(uint32_t*)(sm + O_AH + (uint32_t)r0*STR + col*2) =
                        packh2(fmaxf(acc[mt][n][0] + b2s[col], 0.f),
                               fmaxf(acc[mt][n][1] + b2s[col+1], 0.f));
                    *(uint32_t*)(sm + O_AH + (uint32_t)(r0+8)*STR + col*2) =
                        packh2(fmaxf(acc[mt][n][2] + b2s[col], 0.f),
                               fmaxf(acc[mt][n][3] + b2s[col+1], 0.f));
                }
            }
        }
        __syncwarp();

        // layer 3: relu(h2 @ W3 + b3), mask, column-max
        {
            int ncnt = meta[wid >> 1];
            int rb0  = (wid & 1) * 32;
            #pragma unroll
            for (int nh = 0; nh < 2; nh++) {
                float acc[2][16][4];
                #pragma unroll
                for (int mt = 0; mt < 2; mt++)
                    #pragma unroll
                    for (int n = 0; n < 16; n++)
                        #pragma unroll
                        for (int q = 0; q < 4; q++) acc[mt][n][q] = 0.f;
                #pragma unroll
                for (int k = 0; k < 8; k++) {
                    uint32_t a[2][4];
                    #pragma unroll
                    for (int mt = 0; mt < 2; mt++) {
                        const char* base = sm + O_AH + (uint32_t)(m0 + mt*16 + g4)*STR + k*32 + tig*4;
                        a[mt][0] = *(const uint32_t*)(base);
                        a[mt][1] = *(const uint32_t*)(base + 8*STR);
                        a[mt][2] = *(const uint32_t*)(base + 16);
                        a[mt][3] = *(const uint32_t*)(base + 8*STR + 16);
                    }
                    #pragma unroll
                    for (int n = 0; n < 16; n++) {
                        const char* bb = sm + O_W3T + (uint32_t)(nh*128 + n*8 + g4)*STR + k*32 + tig*4;
                        uint32_t b0 = *(const uint32_t*)(bb);
                        uint32_t b1 = *(const uint32_t*)(bb + 16);
                        mma16816(acc[0][n], a[0], b0, b1);
                        mma16816(acc[1][n], a[1], b0, b1);
                    }
                }
                #pragma unroll
                for (int n = 0; n < 16; n++) {
                    int col = nh*128 + n*8 + tig*2;
                    float bv0 = b3s[col], bv1 = b3s[col+1];
                    float mx0 = -1e30f, mx1 = -1e30f;
                    #pragma unroll
                    for (int mt = 0; mt < 2; mt++) {
                        int rlo = rb0 + mt*16 + g4;
                        bool vlo = rlo < ncnt, vhi = (rlo + 8) < ncnt;
                        if (vlo) {
                            mx0 = fmaxf(mx0, fmaxf(acc[mt][n][0] + bv0, 0.f));
                            mx1 = fmaxf(mx1, fmaxf(acc[mt][n][1] + bv1, 0.f));
                        }
                        if (vhi) {
                            mx0 = fmaxf(mx0, fmaxf(acc[mt][n][2] + bv0, 0.f));
                            mx1 = fmaxf(mx1, fmaxf(acc[mt][n][3] + bv1, 0.f));
                        }
                    }
                    #pragma unroll
                    for (int o = 4; o <= 16; o <<= 1) {
                        mx0 = fmaxf(mx0, __shfl_xor_sync(0xffffffffu, mx0, o));
                        mx1 = fmaxf(mx1, __shfl_xor_sync(0xffffffffu, mx1, o));
                    }
                    if (g4 == 0) {
                        part[wid*256 + col]     = mx0;
                        part[wid*256 + col + 1] = mx1;
                    }
                }
            }
        }
        __syncthreads();

        {
            int col = t;  // wait: t in [0,256) covers all 256 cols
            #pragma unroll
            for (int cl = 0; cl < 4; cl++) {
                float v = fmaxf(part[(2*cl)*256 + col], part[(2*cl + 1)*256 + col]);
                out[(size_t)(c0 + cl)*256 + col] = (meta[cl] > 0) ? v : 0.f;
            }
        }
        __syncthreads();
    }
}

// ============================================================
// 4) Tail outputs
// ============================================================
__global__ void tail_kernel(const float* __restrict__ pos, float* __restrict__ out,
                            int write_tail) {
    int i = blockIdx.x * blockDim.x + threadIdx.x;
    if (i >= NCTR || !write_tail) return;
    int fi = g_idx[i];
    out[POS_OFF + 3*i + 0] = pos[3*fi + 0];
    out[POS_OFF + 3*i + 1] = pos[3*fi + 1];
    out[POS_OFF + 3*i + 2] = pos[3*fi + 2];
    out[BATCH_OFF + i] = (float)(fi >> 12);
    out[SEED_OFF  + i] = (float)fi;
}

// ============================================================
extern "C" void kernel_launch(void* const* d_in, const int* in_sizes, int n_in,
                              void* d_out, int out_size) {
    const float* x   = (const float*)d_in[0];
    const float* pos = (const float*)d_in[1];
    const float* W1  = (const float*)d_in[4];
    const float* b1  = (const float*)d_in[5];
    const float* W2  = (const float*)d_in[6];
    const float* b2  = (const float*)d_in[7];
    const float* W3  = (const float*)d_in[8];
    const float* b3  = (const float*)d_in[9];
    float* out = (float*)d_out;

    cudaFuncSetAttribute(fps_kernel, cudaFuncAttributeMaxDynamicSharedMemorySize, FPS_SMEM);
    cudaFuncSetAttribute(edge_kernel, cudaFuncAttributeMaxDynamicSharedMemorySize, SMEM_EDGE);

    fps_kernel<<<NB, 512, FPS_SMEM>>>(pos);
    nbr_kernel<<<NCTR, 256>>>(pos);
    qb_kernel<<<NB*NPTS/QPB, 128>>>(x, pos, W1, b1);
    edge_kernel<<<148, 256, SMEM_EDGE>>>(pos, W1, W2, b2, W3, b3, out);
    tail_kernel<<<(NCTR + 255)/256, 256>>>(pos, out, out_size >= TOTAL_OUT ? 1 : 0);
}